// round 5
// baseline (speedup 1.0000x reference)
#include <cuda_runtime.h>
#include <math.h>

#define S 2048
#define D 1024
#define NI 13
#define NO 130
#define LN_EPS 1e-5f
#define TAIL_EPS 1e-7f

#define WDCOLS 160                        // 130 cols zero-padded to 160

// k1 smem (NP=7): red float2[8][7][5][32] = 71680 B, then ps float[14][132]
#define RED_BYTES7 (8 * 7 * 5 * 32 * 8)
#define K1_SMEM    (RED_BYTES7 + 14 * 132 * 4)   // 79072

// Scratch (allocation-free rule: __device__ globals)
__device__ float2 g_Wd[D * WDCOLS];   // duplicated {w,w}, zero-padded
__device__ float4 g_lin[NI * S];
__device__ float4 g_ang[NI * S];
__device__ int    g_tcut[NI * S];

__device__ __forceinline__ float sp(float x) {
    return (x > 0.f) ? x + log1pf(expf(-x)) : log1pf(expf(x));
}
__device__ __forceinline__ void ffma2(unsigned long long& acc,
                                      unsigned long long a, unsigned long long w) {
    asm("fma.rn.f32x2 %0, %1, %2, %0;" : "+l"(acc) : "l"(a), "l"(w));
}

// ---------------------------------------------------------------------------
// Kernel 0: pack W into duplicated, zero-padded layout (runs every call; ~1 µs)
// ---------------------------------------------------------------------------
__global__ void k0(const float* __restrict__ W)
{
    int k = blockIdx.x, c = threadIdx.x;
    float v = (c < NO) ? W[k * NO + c] : 0.f;
    g_Wd[k * WDCOLS + c] = make_float2(v, v);
}

// ---------------------------------------------------------------------------
// Kernel 1: fused LayerNorm + GEMM + parameter derivation.
// Template NP = row-pairs per block (rows = 2*NP, pairs (p, p+NP)).
// block (32,8); warp w owns k-slice [128w, 128w+128) for ALL pairs.
// W loads are LDG.64 of pre-duplicated {w,w}; buf index is compile-time so
// wv[] stays in registers (R4's runtime `buf` could demote it to local mem).
// ---------------------------------------------------------------------------
template<int NP>
__global__ void __launch_bounds__(256, 1)
k1(const float* __restrict__ x, const float* __restrict__ minp,
   const float* __restrict__ gamma, const float* __restrict__ beta,
   const float* __restrict__ bias, float* __restrict__ out, int rbase)
{
    extern __shared__ char smraw[];
    float2* xs2 = (float2*)smraw;                  // [NP][1024]
    float2* red = (float2*)smraw;                  // [8][NP][5][32] (reuses xs2)
    float*  ps  = (float*)(smraw + RED_BYTES7);    // [2*NP][132]

    const int tx = threadIdx.x, w = threadIdx.y;
    const int tid = w * 32 + tx;
    const int r0 = rbase + blockIdx.x * 2 * NP;

    // ---- LayerNorm + pack: warp w (< NP) handles rows (r0+w, r0+w+NP) ----
    if (w < NP) {
        const float4* xr0 = (const float4*)(x + (size_t)(r0 + w) * D);
        const float4* xr1 = (const float4*)(x + (size_t)(r0 + w + NP) * D);
        float s1 = 0.f, s2 = 0.f, u1 = 0.f, u2 = 0.f;
        #pragma unroll
        for (int it = 0; it < 8; ++it) {
            float4 a = xr0[it * 32 + tx];
            float4 b = xr1[it * 32 + tx];
            s1 += a.x + a.y + a.z + a.w;
            s2 += a.x * a.x + a.y * a.y + a.z * a.z + a.w * a.w;
            u1 += b.x + b.y + b.z + b.w;
            u2 += b.x * b.x + b.y * b.y + b.z * b.z + b.w * b.w;
        }
        #pragma unroll
        for (int o = 16; o; o >>= 1) {
            s1 += __shfl_xor_sync(0xffffffffu, s1, o);
            s2 += __shfl_xor_sync(0xffffffffu, s2, o);
            u1 += __shfl_xor_sync(0xffffffffu, u1, o);
            u2 += __shfl_xor_sync(0xffffffffu, u2, o);
        }
        const float mu0 = s1 * (1.f / D);
        const float rs0 = rsqrtf(s2 * (1.f / D) - mu0 * mu0 + LN_EPS);
        const float mu1 = u1 * (1.f / D);
        const float rs1 = rsqrtf(u2 * (1.f / D) - mu1 * mu1 + LN_EPS);

        const float4* g4p = (const float4*)gamma;
        const float4* b4p = (const float4*)beta;
        float2* xrow = xs2 + w * 1024;
        #pragma unroll
        for (int it = 0; it < 8; ++it) {
            int e = it * 32 + tx;
            float4 a = xr0[e], b = xr1[e];
            float4 g = g4p[e], be = b4p[e];
            int k = e * 4;
            xrow[k + 0] = make_float2((a.x - mu0) * rs0 * g.x + be.x, (b.x - mu1) * rs1 * g.x + be.x);
            xrow[k + 1] = make_float2((a.y - mu0) * rs0 * g.y + be.y, (b.y - mu1) * rs1 * g.y + be.y);
            xrow[k + 2] = make_float2((a.z - mu0) * rs0 * g.z + be.z, (b.z - mu1) * rs1 * g.z + be.z);
            xrow[k + 3] = make_float2((a.w - mu0) * rs0 * g.w + be.w, (b.w - mu1) * rs1 * g.w + be.w);
        }
    }
    __syncthreads();

    // ---- GEMM: warp w, k in [128w, 128w+128), all NP pairs ----
    const int k0w = w * 128;
    const int kb  = w * 64;
    const unsigned long long* Wdu = (const unsigned long long*)g_Wd;
    const ulonglong2* xsu = (const ulonglong2*)xs2;

    unsigned long long acc[NP][5];
    #pragma unroll
    for (int p = 0; p < NP; ++p)
        #pragma unroll
        for (int c = 0; c < 5; ++c) acc[p][c] = 0ull;

    unsigned long long wv[2][2][5];
    #pragma unroll
    for (int t = 0; t < 2; ++t)
        #pragma unroll
        for (int cg = 0; cg < 5; ++cg)
            wv[0][t][cg] = Wdu[(k0w + t) * WDCOLS + tx + 32 * cg];

    // BUF/NBUF are literals -> wv stays in registers.
    #define GEMM_STEP(ST, BUF, NBUF)                                              \
    {                                                                             \
        if ((ST) < 63) {                                                          \
            _Pragma("unroll")                                                     \
            for (int t = 0; t < 2; ++t)                                           \
                _Pragma("unroll")                                                 \
                for (int cg = 0; cg < 5; ++cg)                                    \
                    wv[NBUF][t][cg] =                                             \
                        Wdu[(k0w + 2 * ((ST) + 1) + t) * WDCOLS + tx + 32 * cg];  \
        }                                                                         \
        ulonglong2 a2[NP];                                                        \
        _Pragma("unroll")                                                         \
        for (int p = 0; p < NP; ++p) a2[p] = xsu[p * 512 + kb + (ST)];            \
        _Pragma("unroll")                                                         \
        for (int cg = 0; cg < 5; ++cg) {                                          \
            unsigned long long w0 = wv[BUF][0][cg];                               \
            _Pragma("unroll")                                                     \
            for (int p = 0; p < NP; ++p) ffma2(acc[p][cg], a2[p].x, w0);          \
        }                                                                         \
        _Pragma("unroll")                                                         \
        for (int cg = 0; cg < 5; ++cg) {                                          \
            unsigned long long w1 = wv[BUF][1][cg];                               \
            _Pragma("unroll")                                                     \
            for (int p = 0; p < NP; ++p) ffma2(acc[p][cg], a2[p].y, w1);          \
        }                                                                         \
    }

    for (int st = 0; st < 64; st += 2) {
        GEMM_STEP(st, 0, 1);
        GEMM_STEP(st + 1, 1, 0);
    }
    #undef GEMM_STEP
    __syncthreads();   // xs2 dead; red may overwrite

    // ---- cross-warp k-slice reduction through smem ----
    #pragma unroll
    for (int p = 0; p < NP; ++p)
        #pragma unroll
        for (int cg = 0; cg < 5; ++cg)
            red[((w * NP + p) * 5 + cg) * 32 + tx] = *(float2*)&acc[p][cg];
    __syncthreads();

    for (int idx = tid; idx < NP * 160; idx += 256) {
        int p = idx / 160, r = idx - p * 160;
        int cg = r >> 5, lane = r & 31;
        int col = cg * 32 + lane;           // cg==4 -> 128+lane
        if (col < NO) {
            float sx = 0.f, sy = 0.f;
            #pragma unroll
            for (int ww = 0; ww < 8; ++ww) {
                float2 v = red[((ww * NP + p) * 5 + cg) * 32 + lane];
                sx += v.x; sy += v.y;
            }
            float bv = bias[col];
            ps[p * 132 + col]        = sx + bv;
            ps[(p + NP) * 132 + col] = sy + bv;
        }
    }
    __syncthreads();

    // ---- derive damped-sinusoid params: 2*NP rows x 13 imus ----
    if (tid < 2 * NP * NI) {
        int il = tid / NI, m = tid - il * NI;
        int i = r0 + il;
        const float* p = ps + il * 132;
        float p0 = p[0 * 13 + m], p1 = p[1 * 13 + m];
        float p2 = p[2 * 13 + m], p3 = p[3 * 13 + m];
        float c   = p[4 * 13 + m], cth   = p[5 * 13 + m];
        float phi = p[6 * 13 + m], phith = p[7 * 13 + m];
        float nb  = p[8 * 13 + m], p9    = p[9 * 13 + m];

        out[m * S + i]          = minp[0] + nb;   // kin added later by k2
        out[NI * S + m * S + i] = sp(p9);         // noise_std

        float dh = 0.5f * sp(p1);
        float om = sqrtf(sp(p0));
        float e  = expf(-dh);
        float4 L;
        L.x = e * cosf(om);  L.y = e * sinf(om);
        L.z = c * cosf(phi); L.w = c * sinf(phi);
        float em = -expm1f(-dh);
        float tl = ceilf(logf(fmaxf(fabsf(c), 1e-30f) / (TAIL_EPS * em)) / dh);

        float dha = 0.5f * sp(p3);
        float oma = sqrtf(sp(p2));
        float ea  = expf(-dha);
        float4 A;
        A.x = ea * cosf(oma);    A.y = ea * sinf(oma);
        A.z = cth * cosf(phith); A.w = cth * sinf(phith);
        float ema = -expm1f(-dha);
        float ta = ceilf(logf(fmaxf(fabsf(cth), 1e-30f) / (TAIL_EPS * ema)) / dha);

        float tmax = fminf(fmaxf(fmaxf(tl, ta), 0.f), (float)S);
        g_lin[m * S + i]  = L;
        g_ang[m * S + i]  = A;
        g_tcut[m * S + i] = (int)tmax;
    }
}

// ---------------------------------------------------------------------------
// Kernel 2: warp-cooperative damped-sinusoid scatter, 2x unrolled (R^64 step).
// grid (64 bands, 13 imus), 128 threads (4 warps), 8 sources per warp.
// 32KB smem -> ~6 resident blocks/SM (R4 had 2.8-wave grid at occ 17%).
// ---------------------------------------------------------------------------
__global__ void __launch_bounds__(128)
k2(float* __restrict__ out)
{
    __shared__ float kin[4][S];   // 32 KB, one private row per warp
    const int tid  = threadIdx.x;
    const int lane = tid & 31, w = tid >> 5;
    const int band = blockIdx.x, m = blockIdx.y;

    float4* kz = (float4*)&kin[0][0];
    for (int idx = tid; idx < 4 * S / 4; idx += 128) kz[idx] = make_float4(0.f, 0.f, 0.f, 0.f);
    __syncthreads();

    float* kw = kin[w];
    const int ibase = band * 32 + w * 8;

    for (int ss = 0; ss < 8; ++ss) {
        const int i  = ibase + ss;
        const int gi = m * S + i;
        const float4 L = g_lin[gi];
        const float4 A = g_ang[gi];
        const int   tc = g_tcut[gi];
        const int jend = min(S, i + tc + 1);

        // product scan: lane l -> R^(l+1)
        float clx = L.x, cly = L.y;
        float cax = A.x, cay = A.y;
        #pragma unroll
        for (int k = 1; k < 32; k <<= 1) {
            float olx = __shfl_up_sync(0xffffffffu, clx, k);
            float oly = __shfl_up_sync(0xffffffffu, cly, k);
            float oax = __shfl_up_sync(0xffffffffu, cax, k);
            float oay = __shfl_up_sync(0xffffffffu, cay, k);
            if (lane >= k) {
                float nlx = olx * clx - oly * cly;
                float nly = olx * cly + oly * clx;
                clx = nlx; cly = nly;
                float nax = oax * cax - oay * cay;
                float nay = oax * cay + oay * cax;
                cax = nax; cay = nay;
            }
        }
        const float r32lx = __shfl_sync(0xffffffffu, clx, 31);
        const float r32ly = __shfl_sync(0xffffffffu, cly, 31);
        const float r32ax = __shfl_sync(0xffffffffu, cax, 31);
        const float r32ay = __shfl_sync(0xffffffffu, cay, 31);
        // R^64 = (R^32)^2
        const float r64lx = r32lx * r32lx - r32ly * r32ly;
        const float r64ly = 2.f * r32lx * r32ly;
        const float r64ax = r32ax * r32ax - r32ay * r32ay;
        const float r64ay = 2.f * r32ax * r32ay;

        // lane l needs R^l: shift down by one, lane 0 = identity
        float plx = __shfl_up_sync(0xffffffffu, clx, 1);
        float ply = __shfl_up_sync(0xffffffffu, cly, 1);
        float pax = __shfl_up_sync(0xffffffffu, cax, 1);
        float pay = __shfl_up_sync(0xffffffffu, cay, 1);
        if (lane == 0) { plx = 1.f; ply = 0.f; pax = 1.f; pay = 0.f; }

        // Ta = state0 * R^l (offset 0); Tb = Ta * R^32 (offset 32)
        float Talx = L.z * plx - L.w * ply;
        float Taly = L.z * ply + L.w * plx;
        float Taax = A.z * pax - A.w * pay;
        float Taay = A.z * pay + A.w * pax;
        float Tblx = Talx * r32lx - Taly * r32ly;
        float Tbly = Talx * r32ly + Taly * r32lx;
        float Tbax = Taax * r32ax - Taay * r32ay;
        float Tbay = Taax * r32ay + Taay * r32ax;

        const int len = jend - i;              // >= 1
        const int nt  = (len + 63) >> 6;
        int j = i + lane;
        for (int it = 0; it < nt; ++it) {
            if (j      < jend) kw[j]      += Taly + Taay;
            if (j + 32 < jend) kw[j + 32] += Tbly + Tbay;
            float n0, n1;
            n0 = Talx * r64lx - Taly * r64ly; n1 = Talx * r64ly + Taly * r64lx;
            Talx = n0; Taly = n1;
            n0 = Taax * r64ax - Taay * r64ay; n1 = Taax * r64ay + Taay * r64ax;
            Taax = n0; Taay = n1;
            n0 = Tblx * r64lx - Tbly * r64ly; n1 = Tblx * r64ly + Tbly * r64lx;
            Tblx = n0; Tbly = n1;
            n0 = Tbax * r64ax - Tbay * r64ay; n1 = Tbax * r64ay + Tbay * r64ax;
            Tbax = n0; Tbay = n1;
            j += 64;
        }
        __syncwarp();
    }
    __syncthreads();

    // reduce 4 private rows, merge into out (cross-block via global atomics)
    float* orow = out + m * S;
    for (int jj = band * 32 + tid; jj < S; jj += 128) {
        float v = kin[0][jj] + kin[1][jj] + kin[2][jj] + kin[3][jj];
        atomicAdd(orow + jj, v);
    }
}

extern "C" void kernel_launch(void* const* d_in, const int* in_sizes, int n_in,
                              void* d_out, int out_size)
{
    const float* x     = (const float*)d_in[0];  // (1, 2048, 1024)
    const float* minp  = (const float*)d_in[1];  // (1,)
    const float* gamma = (const float*)d_in[2];  // (1024,)
    const float* beta  = (const float*)d_in[3];  // (1024,)
    const float* W     = (const float*)d_in[4];  // (1024, 130)
    const float* b     = (const float*)d_in[5];  // (130,)
    float* out = (float*)d_out;                  // (13,2048) out ++ (13,2048) noise_std

    cudaFuncSetAttribute(k1<7>, cudaFuncAttributeMaxDynamicSharedMemorySize, K1_SMEM);
    cudaFuncSetAttribute(k1<2>, cudaFuncAttributeMaxDynamicSharedMemorySize, K1_SMEM);

    k0<<<D, WDCOLS>>>(W);
    // rows [0, 2044) in 146 blocks of 14; rows [2044, 2048) in one 4-row block
    k1<7><<<146, dim3(32, 8), K1_SMEM>>>(x, minp, gamma, beta, b, out, 0);
    k1<2><<<1,   dim3(32, 8), K1_SMEM>>>(x, minp, gamma, beta, b, out, 2044);
    k2<<<dim3(64, NI), 128>>>(out);
}

// round 6
// speedup vs baseline: 1.0025x; 1.0025x over previous
#include <cuda_runtime.h>
#include <math.h>

#define S 2048
#define D 1024
#define NI 13
#define NO 130
#define LN_EPS 1e-5f
#define TAIL_EPS 1e-7f

#define WDCOLS 160                        // 130 cols zero-padded to 160

// k1 smem (NP=7): red float2[8][7][5][32] = 71680 B, then ps float[14][132]
#define RED_BYTES7 (8 * 7 * 5 * 32 * 8)
#define K1_SMEM    (RED_BYTES7 + 14 * 132 * 4)   // 79072

// Scratch (allocation-free rule: __device__ globals)
__device__ float2 g_Wd[D * WDCOLS];   // duplicated {w,w}, zero-padded
__device__ float4 g_lin[NI * S];
__device__ float4 g_ang[NI * S];
__device__ int    g_tcut[NI * S];

__device__ __forceinline__ float sp(float x) {
    return (x > 0.f) ? x + log1pf(expf(-x)) : log1pf(expf(x));
}
__device__ __forceinline__ void ffma2(unsigned long long& acc,
                                      unsigned long long a, unsigned long long w) {
    asm("fma.rn.f32x2 %0, %1, %2, %0;" : "+l"(acc) : "l"(a), "l"(w));
}

// ---------------------------------------------------------------------------
// Kernel 0: pack W into duplicated, zero-padded layout (runs every call; ~1 µs)
// ---------------------------------------------------------------------------
__global__ void k0(const float* __restrict__ W)
{
    int k = blockIdx.x, c = threadIdx.x;
    float v = (c < NO) ? W[k * NO + c] : 0.f;
    g_Wd[k * WDCOLS + c] = make_float2(v, v);
}

// ---------------------------------------------------------------------------
// Kernel 1: fused LayerNorm + GEMM + parameter derivation.
// Template NP = row-pairs per block (rows = 2*NP, pairs (p, p+NP)).
// block (32,8); warp w owns k-slice [128w, 128w+128) for ALL pairs.
// W loads are LDG.64 of pre-duplicated {w,w}; buf index is compile-time so
// wv[] stays in registers (R4's runtime `buf` could demote it to local mem).
// ---------------------------------------------------------------------------
template<int NP>
__global__ void __launch_bounds__(256, 1)
k1(const float* __restrict__ x, const float* __restrict__ minp,
   const float* __restrict__ gamma, const float* __restrict__ beta,
   const float* __restrict__ bias, float* __restrict__ out, int rbase)
{
    extern __shared__ char smraw[];
    float2* xs2 = (float2*)smraw;                  // [NP][1024]
    float2* red = (float2*)smraw;                  // [8][NP][5][32] (reuses xs2)
    float*  ps  = (float*)(smraw + RED_BYTES7);    // [2*NP][132]

    const int tx = threadIdx.x, w = threadIdx.y;
    const int tid = w * 32 + tx;
    const int r0 = rbase + blockIdx.x * 2 * NP;

    // ---- LayerNorm + pack: warp w (< NP) handles rows (r0+w, r0+w+NP) ----
    if (w < NP) {
        const float4* xr0 = (const float4*)(x + (size_t)(r0 + w) * D);
        const float4* xr1 = (const float4*)(x + (size_t)(r0 + w + NP) * D);
        float s1 = 0.f, s2 = 0.f, u1 = 0.f, u2 = 0.f;
        #pragma unroll
        for (int it = 0; it < 8; ++it) {
            float4 a = xr0[it * 32 + tx];
            float4 b = xr1[it * 32 + tx];
            s1 += a.x + a.y + a.z + a.w;
            s2 += a.x * a.x + a.y * a.y + a.z * a.z + a.w * a.w;
            u1 += b.x + b.y + b.z + b.w;
            u2 += b.x * b.x + b.y * b.y + b.z * b.z + b.w * b.w;
        }
        #pragma unroll
        for (int o = 16; o; o >>= 1) {
            s1 += __shfl_xor_sync(0xffffffffu, s1, o);
            s2 += __shfl_xor_sync(0xffffffffu, s2, o);
            u1 += __shfl_xor_sync(0xffffffffu, u1, o);
            u2 += __shfl_xor_sync(0xffffffffu, u2, o);
        }
        const float mu0 = s1 * (1.f / D);
        const float rs0 = rsqrtf(s2 * (1.f / D) - mu0 * mu0 + LN_EPS);
        const float mu1 = u1 * (1.f / D);
        const float rs1 = rsqrtf(u2 * (1.f / D) - mu1 * mu1 + LN_EPS);

        const float4* g4p = (const float4*)gamma;
        const float4* b4p = (const float4*)beta;
        float2* xrow = xs2 + w * 1024;
        #pragma unroll
        for (int it = 0; it < 8; ++it) {
            int e = it * 32 + tx;
            float4 a = xr0[e], b = xr1[e];
            float4 g = g4p[e], be = b4p[e];
            int k = e * 4;
            xrow[k + 0] = make_float2((a.x - mu0) * rs0 * g.x + be.x, (b.x - mu1) * rs1 * g.x + be.x);
            xrow[k + 1] = make_float2((a.y - mu0) * rs0 * g.y + be.y, (b.y - mu1) * rs1 * g.y + be.y);
            xrow[k + 2] = make_float2((a.z - mu0) * rs0 * g.z + be.z, (b.z - mu1) * rs1 * g.z + be.z);
            xrow[k + 3] = make_float2((a.w - mu0) * rs0 * g.w + be.w, (b.w - mu1) * rs1 * g.w + be.w);
        }
    }
    __syncthreads();

    // ---- GEMM: warp w, k in [128w, 128w+128), all NP pairs ----
    const int k0w = w * 128;
    const int kb  = w * 64;
    const unsigned long long* Wdu = (const unsigned long long*)g_Wd;
    const ulonglong2* xsu = (const ulonglong2*)xs2;

    unsigned long long acc[NP][5];
    #pragma unroll
    for (int p = 0; p < NP; ++p)
        #pragma unroll
        for (int c = 0; c < 5; ++c) acc[p][c] = 0ull;

    unsigned long long wv[2][2][5];
    #pragma unroll
    for (int t = 0; t < 2; ++t)
        #pragma unroll
        for (int cg = 0; cg < 5; ++cg)
            wv[0][t][cg] = Wdu[(k0w + t) * WDCOLS + tx + 32 * cg];

    // BUF/NBUF are literals -> wv stays in registers.
    #define GEMM_STEP(ST, BUF, NBUF)                                              \
    {                                                                             \
        if ((ST) < 63) {                                                          \
            _Pragma("unroll")                                                     \
            for (int t = 0; t < 2; ++t)                                           \
                _Pragma("unroll")                                                 \
                for (int cg = 0; cg < 5; ++cg)                                    \
                    wv[NBUF][t][cg] =                                             \
                        Wdu[(k0w + 2 * ((ST) + 1) + t) * WDCOLS + tx + 32 * cg];  \
        }                                                                         \
        ulonglong2 a2[NP];                                                        \
        _Pragma("unroll")                                                         \
        for (int p = 0; p < NP; ++p) a2[p] = xsu[p * 512 + kb + (ST)];            \
        _Pragma("unroll")                                                         \
        for (int cg = 0; cg < 5; ++cg) {                                          \
            unsigned long long w0 = wv[BUF][0][cg];                               \
            _Pragma("unroll")                                                     \
            for (int p = 0; p < NP; ++p) ffma2(acc[p][cg], a2[p].x, w0);          \
        }                                                                         \
        _Pragma("unroll")                                                         \
        for (int cg = 0; cg < 5; ++cg) {                                          \
            unsigned long long w1 = wv[BUF][1][cg];                               \
            _Pragma("unroll")                                                     \
            for (int p = 0; p < NP; ++p) ffma2(acc[p][cg], a2[p].y, w1);          \
        }                                                                         \
    }

    for (int st = 0; st < 64; st += 2) {
        GEMM_STEP(st, 0, 1);
        GEMM_STEP(st + 1, 1, 0);
    }
    #undef GEMM_STEP
    __syncthreads();   // xs2 dead; red may overwrite

    // ---- cross-warp k-slice reduction through smem ----
    #pragma unroll
    for (int p = 0; p < NP; ++p)
        #pragma unroll
        for (int cg = 0; cg < 5; ++cg)
            red[((w * NP + p) * 5 + cg) * 32 + tx] = *(float2*)&acc[p][cg];
    __syncthreads();

    for (int idx = tid; idx < NP * 160; idx += 256) {
        int p = idx / 160, r = idx - p * 160;
        int cg = r >> 5, lane = r & 31;
        int col = cg * 32 + lane;           // cg==4 -> 128+lane
        if (col < NO) {
            float sx = 0.f, sy = 0.f;
            #pragma unroll
            for (int ww = 0; ww < 8; ++ww) {
                float2 v = red[((ww * NP + p) * 5 + cg) * 32 + lane];
                sx += v.x; sy += v.y;
            }
            float bv = bias[col];
            ps[p * 132 + col]        = sx + bv;
            ps[(p + NP) * 132 + col] = sy + bv;
        }
    }
    __syncthreads();

    // ---- derive damped-sinusoid params: 2*NP rows x 13 imus ----
    if (tid < 2 * NP * NI) {
        int il = tid / NI, m = tid - il * NI;
        int i = r0 + il;
        const float* p = ps + il * 132;
        float p0 = p[0 * 13 + m], p1 = p[1 * 13 + m];
        float p2 = p[2 * 13 + m], p3 = p[3 * 13 + m];
        float c   = p[4 * 13 + m], cth   = p[5 * 13 + m];
        float phi = p[6 * 13 + m], phith = p[7 * 13 + m];
        float nb  = p[8 * 13 + m], p9    = p[9 * 13 + m];

        out[m * S + i]          = minp[0] + nb;   // kin added later by k2
        out[NI * S + m * S + i] = sp(p9);         // noise_std

        float dh = 0.5f * sp(p1);
        float om = sqrtf(sp(p0));
        float e  = expf(-dh);
        float4 L;
        L.x = e * cosf(om);  L.y = e * sinf(om);
        L.z = c * cosf(phi); L.w = c * sinf(phi);
        float em = -expm1f(-dh);
        float tl = ceilf(logf(fmaxf(fabsf(c), 1e-30f) / (TAIL_EPS * em)) / dh);

        float dha = 0.5f * sp(p3);
        float oma = sqrtf(sp(p2));
        float ea  = expf(-dha);
        float4 A;
        A.x = ea * cosf(oma);    A.y = ea * sinf(oma);
        A.z = cth * cosf(phith); A.w = cth * sinf(phith);
        float ema = -expm1f(-dha);
        float ta = ceilf(logf(fmaxf(fabsf(cth), 1e-30f) / (TAIL_EPS * ema)) / dha);

        float tmax = fminf(fmaxf(fmaxf(tl, ta), 0.f), (float)S);
        g_lin[m * S + i]  = L;
        g_ang[m * S + i]  = A;
        g_tcut[m * S + i] = (int)tmax;
    }
}

// ---------------------------------------------------------------------------
// Kernel 2: warp-cooperative damped-sinusoid scatter, 2x unrolled (R^64 step).
// grid (64 bands, 13 imus), 128 threads (4 warps), 8 sources per warp.
// 32KB smem -> ~6 resident blocks/SM (R4 had 2.8-wave grid at occ 17%).
// ---------------------------------------------------------------------------
__global__ void __launch_bounds__(128)
k2(float* __restrict__ out)
{
    __shared__ float kin[4][S];   // 32 KB, one private row per warp
    const int tid  = threadIdx.x;
    const int lane = tid & 31, w = tid >> 5;
    const int band = blockIdx.x, m = blockIdx.y;

    float4* kz = (float4*)&kin[0][0];
    for (int idx = tid; idx < 4 * S / 4; idx += 128) kz[idx] = make_float4(0.f, 0.f, 0.f, 0.f);
    __syncthreads();

    float* kw = kin[w];
    const int ibase = band * 32 + w * 8;

    for (int ss = 0; ss < 8; ++ss) {
        const int i  = ibase + ss;
        const int gi = m * S + i;
        const float4 L = g_lin[gi];
        const float4 A = g_ang[gi];
        const int   tc = g_tcut[gi];
        const int jend = min(S, i + tc + 1);

        // product scan: lane l -> R^(l+1)
        float clx = L.x, cly = L.y;
        float cax = A.x, cay = A.y;
        #pragma unroll
        for (int k = 1; k < 32; k <<= 1) {
            float olx = __shfl_up_sync(0xffffffffu, clx, k);
            float oly = __shfl_up_sync(0xffffffffu, cly, k);
            float oax = __shfl_up_sync(0xffffffffu, cax, k);
            float oay = __shfl_up_sync(0xffffffffu, cay, k);
            if (lane >= k) {
                float nlx = olx * clx - oly * cly;
                float nly = olx * cly + oly * clx;
                clx = nlx; cly = nly;
                float nax = oax * cax - oay * cay;
                float nay = oax * cay + oay * cax;
                cax = nax; cay = nay;
            }
        }
        const float r32lx = __shfl_sync(0xffffffffu, clx, 31);
        const float r32ly = __shfl_sync(0xffffffffu, cly, 31);
        const float r32ax = __shfl_sync(0xffffffffu, cax, 31);
        const float r32ay = __shfl_sync(0xffffffffu, cay, 31);
        // R^64 = (R^32)^2
        const float r64lx = r32lx * r32lx - r32ly * r32ly;
        const float r64ly = 2.f * r32lx * r32ly;
        const float r64ax = r32ax * r32ax - r32ay * r32ay;
        const float r64ay = 2.f * r32ax * r32ay;

        // lane l needs R^l: shift down by one, lane 0 = identity
        float plx = __shfl_up_sync(0xffffffffu, clx, 1);
        float ply = __shfl_up_sync(0xffffffffu, cly, 1);
        float pax = __shfl_up_sync(0xffffffffu, cax, 1);
        float pay = __shfl_up_sync(0xffffffffu, cay, 1);
        if (lane == 0) { plx = 1.f; ply = 0.f; pax = 1.f; pay = 0.f; }

        // Ta = state0 * R^l (offset 0); Tb = Ta * R^32 (offset 32)
        float Talx = L.z * plx - L.w * ply;
        float Taly = L.z * ply + L.w * plx;
        float Taax = A.z * pax - A.w * pay;
        float Taay = A.z * pay + A.w * pax;
        float Tblx = Talx * r32lx - Taly * r32ly;
        float Tbly = Talx * r32ly + Taly * r32lx;
        float Tbax = Taax * r32ax - Taay * r32ay;
        float Tbay = Taax * r32ay + Taay * r32ax;

        const int len = jend - i;              // >= 1
        const int nt  = (len + 63) >> 6;
        int j = i + lane;
        for (int it = 0; it < nt; ++it) {
            if (j      < jend) kw[j]      += Taly + Taay;
            if (j + 32 < jend) kw[j + 32] += Tbly + Tbay;
            float n0, n1;
            n0 = Talx * r64lx - Taly * r64ly; n1 = Talx * r64ly + Taly * r64lx;
            Talx = n0; Taly = n1;
            n0 = Taax * r64ax - Taay * r64ay; n1 = Taax * r64ay + Taay * r64ax;
            Taax = n0; Taay = n1;
            n0 = Tblx * r64lx - Tbly * r64ly; n1 = Tblx * r64ly + Tbly * r64lx;
            Tblx = n0; Tbly = n1;
            n0 = Tbax * r64ax - Tbay * r64ay; n1 = Tbax * r64ay + Tbay * r64ax;
            Tbax = n0; Tbay = n1;
            j += 64;
        }
        __syncwarp();
    }
    __syncthreads();

    // reduce 4 private rows, merge into out (cross-block via global atomics)
    float* orow = out + m * S;
    for (int jj = band * 32 + tid; jj < S; jj += 128) {
        float v = kin[0][jj] + kin[1][jj] + kin[2][jj] + kin[3][jj];
        atomicAdd(orow + jj, v);
    }
}

extern "C" void kernel_launch(void* const* d_in, const int* in_sizes, int n_in,
                              void* d_out, int out_size)
{
    const float* x     = (const float*)d_in[0];  // (1, 2048, 1024)
    const float* minp  = (const float*)d_in[1];  // (1,)
    const float* gamma = (const float*)d_in[2];  // (1024,)
    const float* beta  = (const float*)d_in[3];  // (1024,)
    const float* W     = (const float*)d_in[4];  // (1024, 130)
    const float* b     = (const float*)d_in[5];  // (130,)
    float* out = (float*)d_out;                  // (13,2048) out ++ (13,2048) noise_std

    cudaFuncSetAttribute(k1<7>, cudaFuncAttributeMaxDynamicSharedMemorySize, K1_SMEM);
    cudaFuncSetAttribute(k1<2>, cudaFuncAttributeMaxDynamicSharedMemorySize, K1_SMEM);

    k0<<<D, WDCOLS>>>(W);
    // rows [0, 2044) in 146 blocks of 14; rows [2044, 2048) in one 4-row block
    k1<7><<<146, dim3(32, 8), K1_SMEM>>>(x, minp, gamma, beta, b, out, 0);
    k1<2><<<1,   dim3(32, 8), K1_SMEM>>>(x, minp, gamma, beta, b, out, 2044);
    k2<<<dim3(64, NI), 128>>>(out);
}

// round 7
// speedup vs baseline: 1.0031x; 1.0006x over previous
#include <cuda_runtime.h>
#include <math.h>

#define S 2048
#define D 1024
#define NI 13
#define NO 130
#define LN_EPS 1e-5f
#define TAIL_EPS 1e-7f

#define WDCOLS 160                        // 130 cols zero-padded to 160

// k1 smem (NP=7): red float2[8][7][5][32] = 71680 B, then ps float[14][132]
#define RED_BYTES7 (8 * 7 * 5 * 32 * 8)
#define K1_SMEM    (RED_BYTES7 + 14 * 132 * 4)   // 79072

// Scratch (allocation-free rule: __device__ globals)
__device__ float2 g_Wd[D * WDCOLS];   // duplicated {w,w}, zero-padded
__device__ float4 g_lin[NI * S];
__device__ float4 g_ang[NI * S];
__device__ int    g_tcut[NI * S];

__device__ __forceinline__ float sp(float x) {
    return (x > 0.f) ? x + log1pf(expf(-x)) : log1pf(expf(x));
}
__device__ __forceinline__ void ffma2(unsigned long long& acc,
                                      unsigned long long a, unsigned long long w) {
    asm("fma.rn.f32x2 %0, %1, %2, %0;" : "+l"(acc) : "l"(a), "l"(w));
}

// ---------------------------------------------------------------------------
// Kernel 0: pack W into duplicated, zero-padded layout (runs every call; ~1 µs)
// ---------------------------------------------------------------------------
__global__ void k0(const float* __restrict__ W)
{
    int k = blockIdx.x, c = threadIdx.x;
    float v = (c < NO) ? W[k * NO + c] : 0.f;
    g_Wd[k * WDCOLS + c] = make_float2(v, v);
}

// ---------------------------------------------------------------------------
// Kernel 1: fused LayerNorm + GEMM + parameter derivation.
// Template NP = row-pairs per block (rows = 2*NP, pairs (p, p+NP)).
// block (32,8); warp w owns k-slice [128w, 128w+128) for ALL pairs.
// W loads are LDG.64 of pre-duplicated {w,w}; buf index is compile-time so
// wv[] stays in registers (R4's runtime `buf` could demote it to local mem).
// ---------------------------------------------------------------------------
template<int NP>
__global__ void __launch_bounds__(256, 1)
k1(const float* __restrict__ x, const float* __restrict__ minp,
   const float* __restrict__ gamma, const float* __restrict__ beta,
   const float* __restrict__ bias, float* __restrict__ out, int rbase)
{
    extern __shared__ char smraw[];
    float2* xs2 = (float2*)smraw;                  // [NP][1024]
    float2* red = (float2*)smraw;                  // [8][NP][5][32] (reuses xs2)
    float*  ps  = (float*)(smraw + RED_BYTES7);    // [2*NP][132]

    const int tx = threadIdx.x, w = threadIdx.y;
    const int tid = w * 32 + tx;
    const int r0 = rbase + blockIdx.x * 2 * NP;

    // ---- LayerNorm + pack: warp w (< NP) handles rows (r0+w, r0+w+NP) ----
    if (w < NP) {
        const float4* xr0 = (const float4*)(x + (size_t)(r0 + w) * D);
        const float4* xr1 = (const float4*)(x + (size_t)(r0 + w + NP) * D);
        float s1 = 0.f, s2 = 0.f, u1 = 0.f, u2 = 0.f;
        #pragma unroll
        for (int it = 0; it < 8; ++it) {
            float4 a = xr0[it * 32 + tx];
            float4 b = xr1[it * 32 + tx];
            s1 += a.x + a.y + a.z + a.w;
            s2 += a.x * a.x + a.y * a.y + a.z * a.z + a.w * a.w;
            u1 += b.x + b.y + b.z + b.w;
            u2 += b.x * b.x + b.y * b.y + b.z * b.z + b.w * b.w;
        }
        #pragma unroll
        for (int o = 16; o; o >>= 1) {
            s1 += __shfl_xor_sync(0xffffffffu, s1, o);
            s2 += __shfl_xor_sync(0xffffffffu, s2, o);
            u1 += __shfl_xor_sync(0xffffffffu, u1, o);
            u2 += __shfl_xor_sync(0xffffffffu, u2, o);
        }
        const float mu0 = s1 * (1.f / D);
        const float rs0 = rsqrtf(s2 * (1.f / D) - mu0 * mu0 + LN_EPS);
        const float mu1 = u1 * (1.f / D);
        const float rs1 = rsqrtf(u2 * (1.f / D) - mu1 * mu1 + LN_EPS);

        const float4* g4p = (const float4*)gamma;
        const float4* b4p = (const float4*)beta;
        float2* xrow = xs2 + w * 1024;
        #pragma unroll
        for (int it = 0; it < 8; ++it) {
            int e = it * 32 + tx;
            float4 a = xr0[e], b = xr1[e];
            float4 g = g4p[e], be = b4p[e];
            int k = e * 4;
            xrow[k + 0] = make_float2((a.x - mu0) * rs0 * g.x + be.x, (b.x - mu1) * rs1 * g.x + be.x);
            xrow[k + 1] = make_float2((a.y - mu0) * rs0 * g.y + be.y, (b.y - mu1) * rs1 * g.y + be.y);
            xrow[k + 2] = make_float2((a.z - mu0) * rs0 * g.z + be.z, (b.z - mu1) * rs1 * g.z + be.z);
            xrow[k + 3] = make_float2((a.w - mu0) * rs0 * g.w + be.w, (b.w - mu1) * rs1 * g.w + be.w);
        }
    }
    __syncthreads();

    // ---- GEMM: warp w, k in [128w, 128w+128), all NP pairs ----
    const int k0w = w * 128;
    const int kb  = w * 64;
    const unsigned long long* Wdu = (const unsigned long long*)g_Wd;
    const ulonglong2* xsu = (const ulonglong2*)xs2;

    unsigned long long acc[NP][5];
    #pragma unroll
    for (int p = 0; p < NP; ++p)
        #pragma unroll
        for (int c = 0; c < 5; ++c) acc[p][c] = 0ull;

    unsigned long long wv[2][2][5];
    #pragma unroll
    for (int t = 0; t < 2; ++t)
        #pragma unroll
        for (int cg = 0; cg < 5; ++cg)
            wv[0][t][cg] = Wdu[(k0w + t) * WDCOLS + tx + 32 * cg];

    // BUF/NBUF are literals -> wv stays in registers.
    #define GEMM_STEP(ST, BUF, NBUF)                                              \
    {                                                                             \
        if ((ST) < 63) {                                                          \
            _Pragma("unroll")                                                     \
            for (int t = 0; t < 2; ++t)                                           \
                _Pragma("unroll")                                                 \
                for (int cg = 0; cg < 5; ++cg)                                    \
                    wv[NBUF][t][cg] =                                             \
                        Wdu[(k0w + 2 * ((ST) + 1) + t) * WDCOLS + tx + 32 * cg];  \
        }                                                                         \
        ulonglong2 a2[NP];                                                        \
        _Pragma("unroll")                                                         \
        for (int p = 0; p < NP; ++p) a2[p] = xsu[p * 512 + kb + (ST)];            \
        _Pragma("unroll")                                                         \
        for (int cg = 0; cg < 5; ++cg) {                                          \
            unsigned long long w0 = wv[BUF][0][cg];                               \
            _Pragma("unroll")                                                     \
            for (int p = 0; p < NP; ++p) ffma2(acc[p][cg], a2[p].x, w0);          \
        }                                                                         \
        _Pragma("unroll")                                                         \
        for (int cg = 0; cg < 5; ++cg) {                                          \
            unsigned long long w1 = wv[BUF][1][cg];                               \
            _Pragma("unroll")                                                     \
            for (int p = 0; p < NP; ++p) ffma2(acc[p][cg], a2[p].y, w1);          \
        }                                                                         \
    }

    for (int st = 0; st < 64; st += 2) {
        GEMM_STEP(st, 0, 1);
        GEMM_STEP(st + 1, 1, 0);
    }
    #undef GEMM_STEP
    __syncthreads();   // xs2 dead; red may overwrite

    // ---- cross-warp k-slice reduction through smem ----
    #pragma unroll
    for (int p = 0; p < NP; ++p)
        #pragma unroll
        for (int cg = 0; cg < 5; ++cg)
            red[((w * NP + p) * 5 + cg) * 32 + tx] = *(float2*)&acc[p][cg];
    __syncthreads();

    for (int idx = tid; idx < NP * 160; idx += 256) {
        int p = idx / 160, r = idx - p * 160;
        int cg = r >> 5, lane = r & 31;
        int col = cg * 32 + lane;           // cg==4 -> 128+lane
        if (col < NO) {
            float sx = 0.f, sy = 0.f;
            #pragma unroll
            for (int ww = 0; ww < 8; ++ww) {
                float2 v = red[((ww * NP + p) * 5 + cg) * 32 + lane];
                sx += v.x; sy += v.y;
            }
            float bv = bias[col];
            ps[p * 132 + col]        = sx + bv;
            ps[(p + NP) * 132 + col] = sy + bv;
        }
    }
    __syncthreads();

    // ---- derive damped-sinusoid params: 2*NP rows x 13 imus ----
    if (tid < 2 * NP * NI) {
        int il = tid / NI, m = tid - il * NI;
        int i = r0 + il;
        const float* p = ps + il * 132;
        float p0 = p[0 * 13 + m], p1 = p[1 * 13 + m];
        float p2 = p[2 * 13 + m], p3 = p[3 * 13 + m];
        float c   = p[4 * 13 + m], cth   = p[5 * 13 + m];
        float phi = p[6 * 13 + m], phith = p[7 * 13 + m];
        float nb  = p[8 * 13 + m], p9    = p[9 * 13 + m];

        out[m * S + i]          = minp[0] + nb;   // kin added later by k2
        out[NI * S + m * S + i] = sp(p9);         // noise_std

        float dh = 0.5f * sp(p1);
        float om = sqrtf(sp(p0));
        float e  = expf(-dh);
        float4 L;
        L.x = e * cosf(om);  L.y = e * sinf(om);
        L.z = c * cosf(phi); L.w = c * sinf(phi);
        float em = -expm1f(-dh);
        float tl = ceilf(logf(fmaxf(fabsf(c), 1e-30f) / (TAIL_EPS * em)) / dh);

        float dha = 0.5f * sp(p3);
        float oma = sqrtf(sp(p2));
        float ea  = expf(-dha);
        float4 A;
        A.x = ea * cosf(oma);    A.y = ea * sinf(oma);
        A.z = cth * cosf(phith); A.w = cth * sinf(phith);
        float ema = -expm1f(-dha);
        float ta = ceilf(logf(fmaxf(fabsf(cth), 1e-30f) / (TAIL_EPS * ema)) / dha);

        float tmax = fminf(fmaxf(fmaxf(tl, ta), 0.f), (float)S);
        g_lin[m * S + i]  = L;
        g_ang[m * S + i]  = A;
        g_tcut[m * S + i] = (int)tmax;
    }
}

// ---------------------------------------------------------------------------
// Kernel 2: warp-cooperative damped-sinusoid scatter, 2x unrolled (R^64 step).
// grid (64 bands, 13 imus), 128 threads (4 warps), 8 sources per warp.
// 32KB smem -> ~6 resident blocks/SM (R4 had 2.8-wave grid at occ 17%).
// ---------------------------------------------------------------------------
__global__ void __launch_bounds__(128)
k2(float* __restrict__ out)
{
    __shared__ float kin[4][S];   // 32 KB, one private row per warp
    const int tid  = threadIdx.x;
    const int lane = tid & 31, w = tid >> 5;
    const int band = blockIdx.x, m = blockIdx.y;

    float4* kz = (float4*)&kin[0][0];
    for (int idx = tid; idx < 4 * S / 4; idx += 128) kz[idx] = make_float4(0.f, 0.f, 0.f, 0.f);
    __syncthreads();

    float* kw = kin[w];
    const int ibase = band * 32 + w * 8;

    for (int ss = 0; ss < 8; ++ss) {
        const int i  = ibase + ss;
        const int gi = m * S + i;
        const float4 L = g_lin[gi];
        const float4 A = g_ang[gi];
        const int   tc = g_tcut[gi];
        const int jend = min(S, i + tc + 1);

        // product scan: lane l -> R^(l+1)
        float clx = L.x, cly = L.y;
        float cax = A.x, cay = A.y;
        #pragma unroll
        for (int k = 1; k < 32; k <<= 1) {
            float olx = __shfl_up_sync(0xffffffffu, clx, k);
            float oly = __shfl_up_sync(0xffffffffu, cly, k);
            float oax = __shfl_up_sync(0xffffffffu, cax, k);
            float oay = __shfl_up_sync(0xffffffffu, cay, k);
            if (lane >= k) {
                float nlx = olx * clx - oly * cly;
                float nly = olx * cly + oly * clx;
                clx = nlx; cly = nly;
                float nax = oax * cax - oay * cay;
                float nay = oax * cay + oay * cax;
                cax = nax; cay = nay;
            }
        }
        const float r32lx = __shfl_sync(0xffffffffu, clx, 31);
        const float r32ly = __shfl_sync(0xffffffffu, cly, 31);
        const float r32ax = __shfl_sync(0xffffffffu, cax, 31);
        const float r32ay = __shfl_sync(0xffffffffu, cay, 31);
        // R^64 = (R^32)^2
        const float r64lx = r32lx * r32lx - r32ly * r32ly;
        const float r64ly = 2.f * r32lx * r32ly;
        const float r64ax = r32ax * r32ax - r32ay * r32ay;
        const float r64ay = 2.f * r32ax * r32ay;

        // lane l needs R^l: shift down by one, lane 0 = identity
        float plx = __shfl_up_sync(0xffffffffu, clx, 1);
        float ply = __shfl_up_sync(0xffffffffu, cly, 1);
        float pax = __shfl_up_sync(0xffffffffu, cax, 1);
        float pay = __shfl_up_sync(0xffffffffu, cay, 1);
        if (lane == 0) { plx = 1.f; ply = 0.f; pax = 1.f; pay = 0.f; }

        // Ta = state0 * R^l (offset 0); Tb = Ta * R^32 (offset 32)
        float Talx = L.z * plx - L.w * ply;
        float Taly = L.z * ply + L.w * plx;
        float Taax = A.z * pax - A.w * pay;
        float Taay = A.z * pay + A.w * pax;
        float Tblx = Talx * r32lx - Taly * r32ly;
        float Tbly = Talx * r32ly + Taly * r32lx;
        float Tbax = Taax * r32ax - Taay * r32ay;
        float Tbay = Taax * r32ay + Taay * r32ax;

        const int len = jend - i;              // >= 1
        const int nt  = (len + 63) >> 6;
        int j = i + lane;
        for (int it = 0; it < nt; ++it) {
            if (j      < jend) kw[j]      += Taly + Taay;
            if (j + 32 < jend) kw[j + 32] += Tbly + Tbay;
            float n0, n1;
            n0 = Talx * r64lx - Taly * r64ly; n1 = Talx * r64ly + Taly * r64lx;
            Talx = n0; Taly = n1;
            n0 = Taax * r64ax - Taay * r64ay; n1 = Taax * r64ay + Taay * r64ax;
            Taax = n0; Taay = n1;
            n0 = Tblx * r64lx - Tbly * r64ly; n1 = Tblx * r64ly + Tbly * r64lx;
            Tblx = n0; Tbly = n1;
            n0 = Tbax * r64ax - Tbay * r64ay; n1 = Tbax * r64ay + Tbay * r64ax;
            Tbax = n0; Tbay = n1;
            j += 64;
        }
        __syncwarp();
    }
    __syncthreads();

    // reduce 4 private rows, merge into out (cross-block via global atomics)
    float* orow = out + m * S;
    for (int jj = band * 32 + tid; jj < S; jj += 128) {
        float v = kin[0][jj] + kin[1][jj] + kin[2][jj] + kin[3][jj];
        atomicAdd(orow + jj, v);
    }
}

extern "C" void kernel_launch(void* const* d_in, const int* in_sizes, int n_in,
                              void* d_out, int out_size)
{
    const float* x     = (const float*)d_in[0];  // (1, 2048, 1024)
    const float* minp  = (const float*)d_in[1];  // (1,)
    const float* gamma = (const float*)d_in[2];  // (1024,)
    const float* beta  = (const float*)d_in[3];  // (1024,)
    const float* W     = (const float*)d_in[4];  // (1024, 130)
    const float* b     = (const float*)d_in[5];  // (130,)
    float* out = (float*)d_out;                  // (13,2048) out ++ (13,2048) noise_std

    cudaFuncSetAttribute(k1<7>, cudaFuncAttributeMaxDynamicSharedMemorySize, K1_SMEM);
    cudaFuncSetAttribute(k1<2>, cudaFuncAttributeMaxDynamicSharedMemorySize, K1_SMEM);

    k0<<<D, WDCOLS>>>(W);
    // rows [0, 2044) in 146 blocks of 14; rows [2044, 2048) in one 4-row block
    k1<7><<<146, dim3(32, 8), K1_SMEM>>>(x, minp, gamma, beta, b, out, 0);
    k1<2><<<1,   dim3(32, 8), K1_SMEM>>>(x, minp, gamma, beta, b, out, 2044);
    k2<<<dim3(64, NI), 128>>>(out);
}